// round 1
// baseline (speedup 1.0000x reference)
#include <cuda_runtime.h>
#include <math.h>
#include <float.h>

#define BATCH   2
#define SEQL    2048
#define DIMV    1536
#define NHEADS  12
#define HDIM    128
#define NTOK    (BATCH * SEQL)   /* 4096 */
#define EPSV    1e-6f

/* ---- scratch (no allocation allowed) ---- */
__device__ float g_q[NTOK * DIMV];
__device__ float g_k[NTOK * DIMV];
__device__ float g_v[NTOK * DIMV];
__device__ float g_att[NTOK * DIMV];

/* =================== SGEMM:  Y[M,N] = X[M,K] * W[N,K]^T + bias[N] =================== */
#define GBM 128
#define GBN 128
#define GBK 16
#define GPAD 132   /* padded row length in smem (keeps float4 16B alignment, reduces conflicts) */

__global__ __launch_bounds__(256, 2)
void sgemm_nt_bias(const float* __restrict__ X, const float* __restrict__ W,
                   const float* __restrict__ bias, float* __restrict__ Y,
                   int M, int N, int K)
{
    __shared__ float Xs[GBK][GPAD];
    __shared__ float Ws[GBK][GPAD];

    const int bm = blockIdx.y * GBM;
    const int bn = blockIdx.x * GBN;
    const int tid = threadIdx.x;
    const int tx = tid & 15;
    const int ty = tid >> 4;
    const int xr = tid >> 2;          /* 0..63 */
    const int xc = (tid & 3) << 2;    /* 0,4,8,12 */

    float acc[8][8];
#pragma unroll
    for (int i = 0; i < 8; i++)
#pragma unroll
        for (int j = 0; j < 8; j++) acc[i][j] = 0.f;

    const float* Xp = X + (size_t)bm * K;
    const float* Wp = W + (size_t)bn * K;

    for (int k0 = 0; k0 < K; k0 += GBK) {
#pragma unroll
        for (int r = 0; r < 2; r++) {
            int row = xr + r * 64;
            float4 vx = *reinterpret_cast<const float4*>(Xp + (size_t)row * K + k0 + xc);
            Xs[xc + 0][row] = vx.x; Xs[xc + 1][row] = vx.y;
            Xs[xc + 2][row] = vx.z; Xs[xc + 3][row] = vx.w;
            float4 vw = *reinterpret_cast<const float4*>(Wp + (size_t)row * K + k0 + xc);
            Ws[xc + 0][row] = vw.x; Ws[xc + 1][row] = vw.y;
            Ws[xc + 2][row] = vw.z; Ws[xc + 3][row] = vw.w;
        }
        __syncthreads();

#pragma unroll
        for (int k = 0; k < GBK; k++) {
            float a[8], b[8];
#pragma unroll
            for (int i = 0; i < 8; i++) a[i] = Xs[k][ty + 16 * i];
#pragma unroll
            for (int j = 0; j < 8; j++) b[j] = Ws[k][tx + 16 * j];
#pragma unroll
            for (int i = 0; i < 8; i++)
#pragma unroll
                for (int j = 0; j < 8; j++)
                    acc[i][j] = fmaf(a[i], b[j], acc[i][j]);
        }
        __syncthreads();
    }

#pragma unroll
    for (int j = 0; j < 8; j++) {
        float bj = bias[bn + tx + 16 * j];
#pragma unroll
        for (int i = 0; i < 8; i++) {
            Y[(size_t)(bm + ty + 16 * i) * N + (bn + tx + 16 * j)] = acc[i][j] + bj;
        }
    }
}

/* =================== RMSNorm (over DIM=1536) + interleaved-pair RoPE, in place ============== */
/* grid = NTOK blocks, 256 threads; each thread owns 3 adjacent pairs (768 pairs = 1536 elems) */
__global__ __launch_bounds__(256)
void rmsnorm_rope_kernel(float* __restrict__ y, const float* __restrict__ g,
                         const float* __restrict__ freqs)
{
    const int t = blockIdx.x;           /* token id 0..4095 */
    const int s = t & (SEQL - 1);       /* position within sequence */
    const int tid = threadIdx.x;

    float* row = y + (size_t)t * DIMV;

    float v0[3], v1[3];
    float ss = 0.f;
#pragma unroll
    for (int i = 0; i < 3; i++) {
        int p = tid * 3 + i;
        v0[i] = row[2 * p];
        v1[i] = row[2 * p + 1];
        ss += v0[i] * v0[i] + v1[i] * v1[i];
    }
    /* block reduce */
#pragma unroll
    for (int o = 16; o > 0; o >>= 1) ss += __shfl_xor_sync(0xffffffffu, ss, o);
    __shared__ float red[8];
    if ((tid & 31) == 0) red[tid >> 5] = ss;
    __syncthreads();
    float tot = red[0] + red[1] + red[2] + red[3] + red[4] + red[5] + red[6] + red[7];
    float r = rsqrtf(tot * (1.0f / (float)DIMV) + EPSV);

    const float* fr = freqs + (size_t)s * (2 * HDIM);
#pragma unroll
    for (int i = 0; i < 3; i++) {
        int p  = tid * 3 + i;
        int d0 = 2 * p;
        int dh = d0 & (HDIM - 1);       /* within-head even index */
        float c  = fr[dh];
        float sn = fr[HDIM + dh];
        float a  = v0[i] * r * g[d0];
        float bb = v1[i] * r * g[d0 + 1];
        row[d0]     = a * c - bb * sn;
        row[d0 + 1] = bb * c + a * sn;
    }
}

/* =================== flash attention (fp32, online softmax) =================== */
#define ABQ 64
#define ABK 64
#define APAD 132
#define SPAD 65
#define ATT_SMEM ((3 * ABQ * APAD + ABQ * SPAD + 3 * ABQ) * (int)sizeof(float))

__global__ __launch_bounds__(256, 1)
void attention_kernel(const float* __restrict__ Q, const float* __restrict__ Kg_,
                      const float* __restrict__ Vg_, const int* __restrict__ seq_lens,
                      float* __restrict__ O)
{
    extern __shared__ float sm[];
    float* Qs   = sm;
    float* Ks   = Qs + ABQ * APAD;
    float* Vs   = Ks + ABK * APAD;
    float* Ss   = Vs + ABK * APAD;
    float* mrow = Ss + ABQ * SPAD;
    float* lrow = mrow + ABQ;
    float* crow = lrow + ABQ;

    const int qt = blockIdx.x, h = blockIdx.y, b = blockIdx.z;
    const int kvlen = seq_lens[b];
    const int q0 = qt * ABQ;
    const int tid = threadIdx.x;
    const int tx = tid & 15, ty = tid >> 4;

    /* load Q tile [64 x 128] */
    const float* Qgp = Q + ((size_t)(b * SEQL + q0) * DIMV + h * HDIM);
    for (int i = tid; i < ABQ * 32; i += 256) {
        int r = i >> 5, c4 = (i & 31) << 2;
        float4 vq = *reinterpret_cast<const float4*>(Qgp + (size_t)r * DIMV + c4);
        float* dst = Qs + r * APAD + c4;
        dst[0] = vq.x; dst[1] = vq.y; dst[2] = vq.z; dst[3] = vq.w;
    }
    if (tid < ABQ) { mrow[tid] = -FLT_MAX; lrow[tid] = 0.f; }

    float o[4][8];
#pragma unroll
    for (int i = 0; i < 4; i++)
#pragma unroll
        for (int j = 0; j < 8; j++) o[i][j] = 0.f;

    __syncthreads();

    const int ktiles = (kvlen + ABK - 1) / ABK;
    const float scale = 0.08838834764831845f;   /* 1/sqrt(128) */

    for (int kt = 0; kt < ktiles; kt++) {
        const int kb = kt * ABK;
        const float* Kp = Kg_ + ((size_t)(b * SEQL + kb) * DIMV + h * HDIM);
        const float* Vp = Vg_ + ((size_t)(b * SEQL + kb) * DIMV + h * HDIM);
        for (int i = tid; i < ABK * 32; i += 256) {
            int r = i >> 5, c4 = (i & 31) << 2;
            float4 vk = *reinterpret_cast<const float4*>(Kp + (size_t)r * DIMV + c4);
            float* dk = Ks + r * APAD + c4;
            dk[0] = vk.x; dk[1] = vk.y; dk[2] = vk.z; dk[3] = vk.w;
            float4 vv = *reinterpret_cast<const float4*>(Vp + (size_t)r * DIMV + c4);
            float* dv = Vs + r * APAD + c4;
            dv[0] = vv.x; dv[1] = vv.y; dv[2] = vv.z; dv[3] = vv.w;
        }
        __syncthreads();

        /* S = Q K^T (64x64), register micro-tiles 4x4, float4 over d */
        float acc[4][4];
#pragma unroll
        for (int i = 0; i < 4; i++)
#pragma unroll
            for (int j = 0; j < 4; j++) acc[i][j] = 0.f;

        for (int d = 0; d < HDIM; d += 4) {
            float4 a4[4], b4[4];
#pragma unroll
            for (int i = 0; i < 4; i++)
                a4[i] = *reinterpret_cast<const float4*>(&Qs[(ty + 16 * i) * APAD + d]);
#pragma unroll
            for (int j = 0; j < 4; j++)
                b4[j] = *reinterpret_cast<const float4*>(&Ks[(tx + 16 * j) * APAD + d]);
#pragma unroll
            for (int i = 0; i < 4; i++)
#pragma unroll
                for (int j = 0; j < 4; j++) {
                    acc[i][j] = fmaf(a4[i].x, b4[j].x, acc[i][j]);
                    acc[i][j] = fmaf(a4[i].y, b4[j].y, acc[i][j]);
                    acc[i][j] = fmaf(a4[i].z, b4[j].z, acc[i][j]);
                    acc[i][j] = fmaf(a4[i].w, b4[j].w, acc[i][j]);
                }
        }
#pragma unroll
        for (int i = 0; i < 4; i++)
#pragma unroll
            for (int j = 0; j < 4; j++) {
                int rr = ty + 16 * i, cc = tx + 16 * j;
                float sv = acc[i][j] * scale;
                if (kb + cc >= kvlen) sv = -FLT_MAX;
                Ss[rr * SPAD + cc] = sv;
            }
        __syncthreads();

        /* online softmax per row (64 row-threads) */
        if (tid < ABQ) {
            const int rr = tid;
            float mx = -FLT_MAX;
            for (int j = 0; j < ABK; j++) mx = fmaxf(mx, Ss[rr * SPAD + j]);
            float mold = mrow[rr];
            float mnew = fmaxf(mold, mx);
            float corr = __expf(mold - mnew);
            float sum = 0.f;
            for (int j = 0; j < ABK; j++) {
                float pv = __expf(Ss[rr * SPAD + j] - mnew);
                Ss[rr * SPAD + j] = pv;
                sum += pv;
            }
            lrow[rr] = lrow[rr] * corr + sum;
            mrow[rr] = mnew;
            crow[rr] = corr;
        }
        __syncthreads();

        /* O = O*corr + P V */
        float cf[4];
#pragma unroll
        for (int i = 0; i < 4; i++) cf[i] = crow[ty + 16 * i];
#pragma unroll
        for (int i = 0; i < 4; i++)
#pragma unroll
            for (int j = 0; j < 8; j++) o[i][j] *= cf[i];

        for (int jj = 0; jj < ABK; jj++) {
            float p[4], vv[8];
#pragma unroll
            for (int i = 0; i < 4; i++) p[i] = Ss[(ty + 16 * i) * SPAD + jj];
#pragma unroll
            for (int j = 0; j < 8; j++) vv[j] = Vs[jj * APAD + tx + 16 * j];
#pragma unroll
            for (int i = 0; i < 4; i++)
#pragma unroll
                for (int j = 0; j < 8; j++)
                    o[i][j] = fmaf(p[i], vv[j], o[i][j]);
        }
        __syncthreads();
    }

    float inv[4];
#pragma unroll
    for (int i = 0; i < 4; i++) inv[i] = 1.0f / lrow[ty + 16 * i];
#pragma unroll
    for (int i = 0; i < 4; i++)
#pragma unroll
        for (int j = 0; j < 8; j++) {
            O[((size_t)(b * SEQL + q0 + ty + 16 * i) * DIMV) + h * HDIM + tx + 16 * j]
                = o[i][j] * inv[i];
        }
}

/* =================== launch =================== */
extern "C" void kernel_launch(void* const* d_in, const int* in_sizes, int n_in,
                              void* d_out, int out_size)
{
    const float* x     = (const float*)d_in[0];
    const float* wq    = (const float*)d_in[1];
    const float* bq    = (const float*)d_in[2];
    const float* wk    = (const float*)d_in[3];
    const float* bk    = (const float*)d_in[4];
    const float* wv    = (const float*)d_in[5];
    const float* bv    = (const float*)d_in[6];
    const float* wo    = (const float*)d_in[7];
    const float* bo    = (const float*)d_in[8];
    const float* gq    = (const float*)d_in[9];
    const float* gk    = (const float*)d_in[10];
    const float* freqs = (const float*)d_in[11];
    const int*   seq_lens = (const int*)d_in[12];
    float* out = (float*)d_out;

    float *qp, *kp, *vp, *ap;
    cudaGetSymbolAddress((void**)&qp, g_q);
    cudaGetSymbolAddress((void**)&kp, g_k);
    cudaGetSymbolAddress((void**)&vp, g_v);
    cudaGetSymbolAddress((void**)&ap, g_att);

    cudaFuncSetAttribute(attention_kernel,
                         cudaFuncAttributeMaxDynamicSharedMemorySize, ATT_SMEM);

    dim3 ggrid(DIMV / GBN, NTOK / GBM);   /* (12, 32) */

    sgemm_nt_bias<<<ggrid, 256>>>(x, wq, bq, qp, NTOK, DIMV, DIMV);
    sgemm_nt_bias<<<ggrid, 256>>>(x, wk, bk, kp, NTOK, DIMV, DIMV);
    sgemm_nt_bias<<<ggrid, 256>>>(x, wv, bv, vp, NTOK, DIMV, DIMV);

    rmsnorm_rope_kernel<<<NTOK, 256>>>(qp, gq, freqs);
    rmsnorm_rope_kernel<<<NTOK, 256>>>(kp, gk, freqs);

    attention_kernel<<<dim3(SEQL / ABQ, NHEADS, BATCH), 256, ATT_SMEM>>>(
        qp, kp, vp, seq_lens, ap);

    sgemm_nt_bias<<<ggrid, 256>>>(ap, wo, bo, out, NTOK, DIMV, DIMV);
}

// round 7
// speedup vs baseline: 3.0817x; 3.0817x over previous
#include <cuda_runtime.h>
#include <math.h>
#include <float.h>
#include <stdint.h>

#define BATCH   2
#define SEQL    2048
#define DIMV    1536
#define NHEADS  12
#define HDIM    128
#define NTOK    (BATCH * SEQL)
#define EPSV    1e-6f

/* ---- scratch ---- */
__device__ float g_q[NTOK * DIMV];
__device__ float g_k[NTOK * DIMV];
__device__ float g_v[NTOK * DIMV];
__device__ float g_att[NTOK * DIMV];

__device__ __forceinline__ uint32_t f2tf(float x) {
    uint32_t u;
    asm("cvt.rna.tf32.f32 %0, %1;" : "=r"(u) : "f"(x));
    return u;
}

/* D += A(m16k8) * B(k8n8), tf32 */
__device__ __forceinline__ void mma8(float* d, const uint32_t* a, const uint32_t* b) {
    asm volatile(
        "mma.sync.aligned.m16n8k8.row.col.f32.tf32.tf32.f32 "
        "{%0,%1,%2,%3},{%4,%5,%6,%7},{%8,%9},{%0,%1,%2,%3};"
        : "+f"(d[0]), "+f"(d[1]), "+f"(d[2]), "+f"(d[3])
        : "r"(a[0]), "r"(a[1]), "r"(a[2]), "r"(a[3]), "r"(b[0]), "r"(b[1]));
}

/* =================== tf32 GEMM: Y[M,N] = X[M,K] W[N,K]^T + bias =================== */
/* block 128x128, K-tile 32; 8 warps as 2(m) x 4(n); warp 64x32; 16 MMAs/warp/kstep */
#define TBK 32
#define XST 36   /* 32 + 4; stride mod 32 == 4 -> conflict-free frag loads */

__global__ __launch_bounds__(256, 2)
void gemm3_tf32(const float* __restrict__ X,
                const float* __restrict__ W0, const float* __restrict__ W1, const float* __restrict__ W2,
                const float* __restrict__ B0, const float* __restrict__ B1, const float* __restrict__ B2,
                float* __restrict__ Y0, float* __restrict__ Y1, float* __restrict__ Y2,
                int M, int N, int K)
{
    __shared__ uint32_t Xs[128 * XST];
    __shared__ uint32_t Ws[128 * XST];

    const int z = blockIdx.z;
    const float* W  = (z == 0) ? W0 : ((z == 1) ? W1 : W2);
    const float* Bb = (z == 0) ? B0 : ((z == 1) ? B1 : B2);
    float*       Y  = (z == 0) ? Y0 : ((z == 1) ? Y1 : Y2);

    const int bm = blockIdx.y * 128, bn = blockIdx.x * 128;
    const int tid = threadIdx.x, lane = tid & 31, wid = tid >> 5;
    const int wm = wid >> 2, wn = wid & 3;
    const int g = lane >> 2, t = lane & 3;

    float acc[4][4][4];
#pragma unroll
    for (int i = 0; i < 4; i++)
#pragma unroll
        for (int j = 0; j < 4; j++)
#pragma unroll
            for (int r = 0; r < 4; r++) acc[i][j][r] = 0.f;

    const int lr = tid >> 3;          /* 0..31 */
    const int lc = (tid & 7) << 2;    /* 0,4,..,28 */

    for (int k0 = 0; k0 < K; k0 += TBK) {
#pragma unroll
        for (int p = 0; p < 4; p++) {
            int row = lr + p * 32;
            float4 vx = *(const float4*)&X[(size_t)(bm + row) * K + k0 + lc];
            *(uint4*)&Xs[row * XST + lc] =
                make_uint4(f2tf(vx.x), f2tf(vx.y), f2tf(vx.z), f2tf(vx.w));
            float4 vw = *(const float4*)&W[(size_t)(bn + row) * K + k0 + lc];
            *(uint4*)&Ws[row * XST + lc] =
                make_uint4(f2tf(vw.x), f2tf(vw.y), f2tf(vw.z), f2tf(vw.w));
        }
        __syncthreads();

#pragma unroll
        for (int ks = 0; ks < 4; ks++) {
            const int kk = ks * 8;
            uint32_t af[4][4], bf[4][2];
#pragma unroll
            for (int mt = 0; mt < 4; mt++) {
                int r = wm * 64 + mt * 16 + g;
                af[mt][0] = Xs[r * XST + kk + t];
                af[mt][1] = Xs[(r + 8) * XST + kk + t];
                af[mt][2] = Xs[r * XST + kk + t + 4];
                af[mt][3] = Xs[(r + 8) * XST + kk + t + 4];
            }
#pragma unroll
            for (int nt = 0; nt < 4; nt++) {
                int n = wn * 32 + nt * 8 + g;
                bf[nt][0] = Ws[n * XST + kk + t];
                bf[nt][1] = Ws[n * XST + kk + t + 4];
            }
#pragma unroll
            for (int mt = 0; mt < 4; mt++)
#pragma unroll
                for (int nt = 0; nt < 4; nt++)
                    mma8(acc[mt][nt], af[mt], bf[nt]);
        }
        __syncthreads();
    }

#pragma unroll
    for (int mt = 0; mt < 4; mt++) {
        int r = bm + wm * 64 + mt * 16 + g;
#pragma unroll
        for (int nt = 0; nt < 4; nt++) {
            int c = bn + wn * 32 + nt * 8 + 2 * t;
            float b0v = Bb[c], b1v = Bb[c + 1];
            *(float2*)&Y[(size_t)r * N + c] =
                make_float2(acc[mt][nt][0] + b0v, acc[mt][nt][1] + b1v);
            *(float2*)&Y[(size_t)(r + 8) * N + c] =
                make_float2(acc[mt][nt][2] + b0v, acc[mt][nt][3] + b1v);
        }
    }
}

/* =================== RMSNorm + RoPE =================== */
__global__ __launch_bounds__(256)
void rmsnorm_rope_kernel(float* __restrict__ y, const float* __restrict__ g,
                         const float* __restrict__ freqs)
{
    const int t = blockIdx.x;
    const int s = t & (SEQL - 1);
    const int tid = threadIdx.x;

    float* row = y + (size_t)t * DIMV;

    float v0[3], v1[3];
    float ss = 0.f;
#pragma unroll
    for (int i = 0; i < 3; i++) {
        int p = tid * 3 + i;
        v0[i] = row[2 * p];
        v1[i] = row[2 * p + 1];
        ss += v0[i] * v0[i] + v1[i] * v1[i];
    }
#pragma unroll
    for (int o = 16; o > 0; o >>= 1) ss += __shfl_xor_sync(0xffffffffu, ss, o);
    __shared__ float red[8];
    if ((tid & 31) == 0) red[tid >> 5] = ss;
    __syncthreads();
    float tot = red[0] + red[1] + red[2] + red[3] + red[4] + red[5] + red[6] + red[7];
    float r = rsqrtf(tot * (1.0f / (float)DIMV) + EPSV);

    const float* fr = freqs + (size_t)s * (2 * HDIM);
#pragma unroll
    for (int i = 0; i < 3; i++) {
        int p  = tid * 3 + i;
        int d0 = 2 * p;
        int dh = d0 & (HDIM - 1);
        float c  = fr[dh];
        float sn = fr[HDIM + dh];
        float a  = v0[i] * r * g[d0];
        float bb = v1[i] * r * g[d0 + 1];
        row[d0]     = a * c - bb * sn;
        row[d0 + 1] = bb * c + a * sn;
    }
}

/* =================== flash attention, tf32 mma =================== */
#define AQ 64
#define AK 64
#define QST 132   /* mod 32 == 4 */
#define VST 136   /* mod 32 == 8 */
#define SST 68    /* mod 32 == 4 */
#define OFF_Q 0
#define OFF_K (64 * QST)            /* 8448  */
#define OFF_V (OFF_K + 64 * QST)    /* 16896 */
#define OFF_S (OFF_V + 64 * VST)    /* 25600 */
#define OFF_M (OFF_S + 64 * SST)    /* 29952 */
#define OFF_L (OFF_M + 64)
#define OFF_C (OFF_L + 64)
#define ATT_WORDS (OFF_C + 64)
#define ATT_SMEM (ATT_WORDS * 4)

__global__ __launch_bounds__(256, 1)
void attn_tf32(const float* __restrict__ Q, const float* __restrict__ Kg,
               const float* __restrict__ Vg, const int* __restrict__ seq_lens,
               float* __restrict__ O)
{
    extern __shared__ uint32_t sm[];
    uint32_t* Qs = sm + OFF_Q;
    uint32_t* Ks = sm + OFF_K;
    uint32_t* Vs = sm + OFF_V;
    uint32_t* Su = sm + OFF_S;
    float* Ss   = (float*)(sm + OFF_S);
    float* mrow = (float*)(sm + OFF_M);
    float* lrow = (float*)(sm + OFF_L);
    float* crow = (float*)(sm + OFF_C);

    const int qt = blockIdx.x, h = blockIdx.y, b = blockIdx.z;
    const int kvlen = seq_lens[b];
    const int q0 = qt * AQ;
    const int tid = threadIdx.x, lane = tid & 31, wid = tid >> 5;
    const int wm = wid >> 2, wn = wid & 3;
    const int g = lane >> 2, t = lane & 3;

    const float* Qg = Q + ((size_t)(b * SEQL + q0) * DIMV + h * HDIM);
    for (int i = tid; i < AQ * 32; i += 256) {
        int r = i >> 5, c4 = (i & 31) << 2;
        float4 v = *(const float4*)&Qg[(size_t)r * DIMV + c4];
        *(uint4*)&Qs[r * QST + c4] = make_uint4(f2tf(v.x), f2tf(v.y), f2tf(v.z), f2tf(v.w));
    }
    if (tid < AQ) { mrow[tid] = -FLT_MAX; lrow[tid] = 0.f; }

    float o[2][4][4];
#pragma unroll
    for (int i = 0; i < 2; i++)
#pragma unroll
        for (int j = 0; j < 4; j++)
#pragma unroll
            for (int r = 0; r < 4; r++) o[i][j][r] = 0.f;

    const int ktiles = (kvlen + AK - 1) / AK;
    const float scale = 0.08838834764831845f;

    for (int kt = 0; kt < ktiles; kt++) {
        const int kb = kt * AK;
        const float* Kp = Kg + ((size_t)(b * SEQL + kb) * DIMV + h * HDIM);
        const float* Vp = Vg + ((size_t)(b * SEQL + kb) * DIMV + h * HDIM);
        for (int i = tid; i < AK * 32; i += 256) {
            int r = i >> 5, c4 = (i & 31) << 2;
            float4 vk = *(const float4*)&Kp[(size_t)r * DIMV + c4];
            *(uint4*)&Ks[r * QST + c4] = make_uint4(f2tf(vk.x), f2tf(vk.y), f2tf(vk.z), f2tf(vk.w));
            float4 vv = *(const float4*)&Vp[(size_t)r * DIMV + c4];
            *(uint4*)&Vs[r * VST + c4] = make_uint4(f2tf(vv.x), f2tf(vv.y), f2tf(vv.z), f2tf(vv.w));
        }
        __syncthreads();

        /* ---- S = Q K^T : warp tile 32(q) x 16(kv) ---- */
        float s[2][2][4];
#pragma unroll
        for (int i = 0; i < 2; i++)
#pragma unroll
            for (int j = 0; j < 2; j++)
#pragma unroll
                for (int r = 0; r < 4; r++) s[i][j][r] = 0.f;

#pragma unroll
        for (int kk = 0; kk < HDIM; kk += 8) {
            uint32_t af[2][4], bf[2][2];
#pragma unroll
            for (int mt = 0; mt < 2; mt++) {
                int r = wm * 32 + mt * 16 + g;
                af[mt][0] = Qs[r * QST + kk + t];
                af[mt][1] = Qs[(r + 8) * QST + kk + t];
                af[mt][2] = Qs[r * QST + kk + t + 4];
                af[mt][3] = Qs[(r + 8) * QST + kk + t + 4];
            }
#pragma unroll
            for (int nt = 0; nt < 2; nt++) {
                int n = wn * 16 + nt * 8 + g;
                bf[nt][0] = Ks[n * QST + kk + t];
                bf[nt][1] = Ks[n * QST + kk + t + 4];
            }
#pragma unroll
            for (int mt = 0; mt < 2; mt++)
#pragma unroll
                for (int nt = 0; nt < 2; nt++)
                    mma8(s[mt][nt], af[mt], bf[nt]);
        }
#pragma unroll
        for (int mt = 0; mt < 2; mt++) {
            int r = wm * 32 + mt * 16 + g;
#pragma unroll
            for (int nt = 0; nt < 2; nt++) {
                int c = wn * 16 + nt * 8 + 2 * t;
                Ss[r * SST + c]           = s[mt][nt][0] * scale;
                Ss[r * SST + c + 1]       = s[mt][nt][1] * scale;
                Ss[(r + 8) * SST + c]     = s[mt][nt][2] * scale;
                Ss[(r + 8) * SST + c + 1] = s[mt][nt][3] * scale;
            }
        }
        __syncthreads();

        /* ---- online softmax: 4 threads per row ---- */
        {
            const int row = tid >> 2, part = tid & 3, cb = part * 16;
            float vals[16];
            float mx = -FLT_MAX;
#pragma unroll
            for (int j = 0; j < 16; j++) {
                int c = cb + j;
                float v = (kb + c < kvlen) ? Ss[row * SST + c] : -FLT_MAX;
                vals[j] = v;
                mx = fmaxf(mx, v);
            }
            mx = fmaxf(mx, __shfl_xor_sync(0xffffffffu, mx, 1));
            mx = fmaxf(mx, __shfl_xor_sync(0xffffffffu, mx, 2));
            float mold = mrow[row];
            float mnew = fmaxf(mold, mx);
            float sum = 0.f;
#pragma unroll
            for (int j = 0; j < 16; j++) {
                float p = __expf(vals[j] - mnew);
                sum += p;
                Su[row * SST + cb + j] = f2tf(p);
            }
            sum += __shfl_xor_sync(0xffffffffu, sum, 1);
            sum += __shfl_xor_sync(0xffffffffu, sum, 2);
            if (part == 0) {
                float corr = __expf(mold - mnew);
                lrow[row] = lrow[row] * corr + sum;
                mrow[row] = mnew;
                crow[row] = corr;
            }
        }
        __syncthreads();

        /* ---- O = O*corr + P V : warp tile 32(q) x 32(d) ---- */
#pragma unroll
        for (int mt = 0; mt < 2; mt++) {
            int r = wm * 32 + mt * 16 + g;
            float c0 = crow[r], c1 = crow[r + 8];
#pragma unroll
            for (int nt = 0; nt < 4; nt++) {
                o[mt][nt][0] *= c0; o[mt][nt][1] *= c0;
                o[mt][nt][2] *= c1; o[mt][nt][3] *= c1;
            }
        }
#pragma unroll
        for (int kk = 0; kk < AK; kk += 8) {
            uint32_t af[2][4], bf[4][2];
#pragma unroll
            for (int mt = 0; mt < 2; mt++) {
                int r = wm * 32 + mt * 16 + g;
                af[mt][0] = Su[r * SST + kk + t];
                af[mt][1] = Su[(r + 8) * SST + kk + t];
                af[mt][2] = Su[r * SST + kk + t + 4];
                af[mt][3] = Su[(r + 8) * SST + kk + t + 4];
            }
#pragma unroll
            for (int nt = 0; nt < 4; nt++) {
                int n = wn * 32 + nt * 8 + g;
                bf[nt][0] = Vs[(kk + t) * VST + n];
                bf[nt][1] = Vs[(kk + t + 4) * VST + n];
            }
#pragma unroll
            for (int mt = 0; mt < 2; mt++)
#pragma unroll
                for (int nt = 0; nt < 4; nt++)
                    mma8(o[mt][nt], af[mt], bf[nt]);
        }
        __syncthreads();
    }

#pragma unroll
    for (int mt = 0; mt < 2; mt++) {
        int r = wm * 32 + mt * 16 + g;
        float i0 = 1.0f / lrow[r], i1 = 1.0f / lrow[r + 8];
#pragma unroll
        for (int nt = 0; nt < 4; nt++) {
            int c = wn * 32 + nt * 8 + 2 * t;
            *(float2*)&O[((size_t)(b * SEQL + q0 + r)) * DIMV + h * HDIM + c] =
                make_float2(o[mt][nt][0] * i0, o[mt][nt][1] * i0);
            *(float2*)&O[((size_t)(b * SEQL + q0 + r + 8)) * DIMV + h * HDIM + c] =
                make_float2(o[mt][nt][2] * i1, o[mt][nt][3] * i1);
        }
    }
}

/* =================== launch =================== */
extern "C" void kernel_launch(void* const* d_in, const int* in_sizes, int n_in,
                              void* d_out, int out_size)
{
    const float* x     = (const float*)d_in[0];
    const float* wq    = (const float*)d_in[1];
    const float* bq    = (const float*)d_in[2];
    const float* wk    = (const float*)d_in[3];
    const float* bk    = (const float*)d_in[4];
    const float* wv    = (const float*)d_in[5];
    const float* bv    = (const float*)d_in[6];
    const float* wo    = (const float*)d_in[7];
    const float* bo    = (const float*)d_in[8];
    const float* gq    = (const float*)d_in[9];
    const float* gk    = (const float*)d_in[10];
    const float* freqs = (const float*)d_in[11];
    const int*   seq_lens = (const int*)d_in[12];
    float* out = (float*)d_out;

    float *qp, *kp, *vp, *ap;
    cudaGetSymbolAddress((void**)&qp, g_q);
    cudaGetSymbolAddress((void**)&kp, g_k);
    cudaGetSymbolAddress((void**)&vp, g_v);
    cudaGetSymbolAddress((void**)&ap, g_att);

    cudaFuncSetAttribute(attn_tf32,
                         cudaFuncAttributeMaxDynamicSharedMemorySize, ATT_SMEM);

    /* fused QKV projection: grid.z picks weight/bias/output */
    gemm3_tf32<<<dim3(DIMV / 128, NTOK / 128, 3), 256>>>(
        x, wq, wk, wv, bq, bk, bv, qp, kp, vp, NTOK, DIMV, DIMV);

    rmsnorm_rope_kernel<<<NTOK, 256>>>(qp, gq, freqs);
    rmsnorm_rope_kernel<<<NTOK, 256>>>(kp, gk, freqs);

    attn_tf32<<<dim3(SEQL / AQ, NHEADS, BATCH), 256, ATT_SMEM>>>(
        qp, kp, vp, seq_lens, ap);

    /* output projection */
    gemm3_tf32<<<dim3(DIMV / 128, NTOK / 128, 1), 256>>>(
        ap, wo, wo, wo, bo, bo, bo, out, out, out, NTOK, DIMV, DIMV);
}